// round 15
// baseline (speedup 1.0000x reference)
#include <cuda_runtime.h>
#include <cuda.h>
#include <cstdint>

#define WIRE_DIM   32
#define NUM_WIRES  64
#define ROW_ELEMS  (NUM_WIRES * WIRE_DIM)   // 2048 floats = 8 KB per batch row
#define WPB        8                        // warps per block = 4 pairs
#define PAIRS      (WPB / 2)
#define STAGES     2                        // ring depth per pair (full rows)
#define ITERS      5                        // rows per pair
#define NTHREADS   (WPB * 32)
#define RPB        (PAIRS * ITERS)          // 20 rows per block
#define ROW_BYTES  8192
#define HALF_BYTES 4096

typedef unsigned long long u64;

// ---- packed f32x2 helpers ----
__device__ __forceinline__ u64 pack2f(float lo, float hi) {
    u64 r; asm("mov.b64 %0, {%1, %2};" : "=l"(r) : "f"(lo), "f"(hi)); return r;
}
__device__ __forceinline__ void ffma2(u64 &d, u64 a, u64 b) {
    asm("fma.rn.f32x2 %0, %1, %2, %0;" : "+l"(d) : "l"(a), "l"(b));
}
__device__ __forceinline__ float2 unpack2(u64 v) {
    float2 f; asm("mov.b64 {%0, %1}, %2;" : "=f"(f.x), "=f"(f.y) : "l"(v)); return f;
}

// ---- mbarrier / TMA helpers ----
__device__ __forceinline__ void mbar_init(uint32_t mb, uint32_t cnt) {
    asm volatile("mbarrier.init.shared.b64 [%0], %1;" :: "r"(mb), "r"(cnt) : "memory");
}
__device__ __forceinline__ void mbar_expect_tx(uint32_t mb, uint32_t bytes) {
    asm volatile("mbarrier.arrive.expect_tx.shared.b64 _, [%0], %1;"
                 :: "r"(mb), "r"(bytes) : "memory");
}
__device__ __forceinline__ void mbar_wait(uint32_t mb, uint32_t parity) {
    asm volatile(
        "{\n\t.reg .pred P;\n"
        "LW_%=:\n\t"
        "mbarrier.try_wait.parity.acquire.cta.shared::cta.b64 P, [%0], %1, 0x989680;\n\t"
        "@P bra LD_%=;\n\t"
        "bra LW_%=;\n"
        "LD_%=:\n\t}"
        :: "r"(mb), "r"(parity) : "memory");
}
__device__ __forceinline__ void tma_load_half(uint32_t dst, const CUtensorMap* map,
                                              int wire_y, uint32_t mb) {
    asm volatile(
        "cp.async.bulk.tensor.2d.shared::cta.global.tile.mbarrier::complete_tx::bytes "
        "[%0], [%1, {%2, %3}], [%4];"
        :: "r"(dst), "l"(map), "r"(0), "r"(wire_y), "r"(mb) : "memory");
}

// ---- weights in constant memory ----
struct CPack {
    u64   Wlow[160];    // (W1[2p][h], W1[2p+1][h])       rows 0..31  (person half)
    u64   Whigh[160];   // (W1[32+2p][h], W1[32+2p+1][h]) rows 32..63 (wire half)
    float b1[10];
    float W2[10];
    float b2;
    float pad[5];
};
__constant__ CPack cc;
__device__   CPack g_pack;

__global__ void prep_kernel(const float* __restrict__ W1,
                            const float* __restrict__ b1,
                            const float* __restrict__ W2,
                            const float* __restrict__ b2)
{
    int i = threadIdx.x;
    if (i < 160) {
        int p = i / 10, h = i - 10 * p;
        g_pack.Wlow[i]  = pack2f(W1[(2 * p) * 10 + h],      W1[(2 * p + 1) * 10 + h]);
        g_pack.Whigh[i] = pack2f(W1[(32 + 2 * p) * 10 + h], W1[(32 + 2 * p + 1) * 10 + h]);
    } else if (i < 170) {
        int h = i - 160;
        g_pack.b1[h] = b1[h];
        g_pack.W2[h] = W2[h];
    } else if (i == 170) {
        g_pack.b2 = b2[0];
    }
}

__global__ __launch_bounds__(NTHREADS, 3)
void trainer_kernel(const __grid_constant__ CUtensorMap tmap,
                    const int* __restrict__ tests_i32,
                    float* __restrict__ out,
                    int B)
{
    extern __shared__ char dynraw[];                 // PAIRS*STAGES*8KB + 1KB slack
    __shared__ __align__(8)  u64   mbar[PAIRS][STAGES];
    __shared__ __align__(16) float sex[PAIRS][2][4]; // per-warp {m, s, cand}

    const int tid  = threadIdx.x;
    const int warp = tid >> 5;
    const int lane = tid & 31;
    const int pair = warp >> 1;
    const int q    = warp & 1;                       // wires [32q, 32q+32)

    // 1024B-align the ring base (SW128 atom alignment)
    uint32_t base0 = (uint32_t)__cvta_generic_to_shared(dynraw);
    uint32_t padb  = ((base0 + 1023u) & ~1023u) - base0;
    float*   xall  = (float*)(dynraw + padb);
    const uint32_t xall_s = base0 + padb;

    if (tid == 0) {
        #pragma unroll
        for (int p = 0; p < PAIRS; p++)
            #pragma unroll
            for (int s = 0; s < STAGES; s++)
                mbar_init((uint32_t)__cvta_generic_to_shared(&mbar[p][s]), 2);
    }
    asm volatile("fence.proxy.async.shared::cta;" ::: "memory");
    __syncthreads();                                  // barriers visible; last block sync

    // --- detect tests dtype (int64 pairs have zero high-words at odd slots) ---
    int hvv = tests_i32[2 * lane + 1];
    #pragma unroll
    for (int o = 16; o > 0; o >>= 1) hvv |= __shfl_xor_sync(0xffffffffu, hvv, o);
    const bool is_i64 = (hvv == 0);

    const int rbase = (blockIdx.x * PAIRS + pair) * ITERS;
    uint32_t mb_s[STAGES], buf_s[STAGES];
    #pragma unroll
    for (int s = 0; s < STAGES; s++) {
        mb_s[s]  = (uint32_t)__cvta_generic_to_shared(&mbar[pair][s]);
        buf_s[s] = xall_s + (uint32_t)((pair * STAGES + s) * ROW_BYTES);
    }
    const uint32_t half_off = (uint32_t)(q * HALF_BYTES);

    // prologue: rows rbase, rbase+1 -> stages 0, 1 (each warp loads its half)
    if (lane == 0) {
        if (rbase < B) {
            mbar_expect_tx(mb_s[0], HALF_BYTES);
            tma_load_half(buf_s[0] + half_off, &tmap, rbase * NUM_WIRES + 32 * q, mb_s[0]);
        }
        if (rbase + 1 < B && ITERS > 1) {
            mbar_expect_tx(mb_s[1], HALF_BYTES);
            tma_load_half(buf_s[1] + half_off, &tmap, (rbase + 1) * NUM_WIRES + 32 * q, mb_s[1]);
        }
    }

    const float b2v = cc.b2;
    const int lw = lane & 7;                         // swizzle key of wire 32q+lane

    #pragma unroll
    for (int i = 0; i < ITERS; i++) {
        const int r = rbase + i;
        if (r >= B) break;

        const int st = i & 1;
        mbar_wait(mb_s[st], (i >> 1) & 1);           // full row i landed (both halves)
        const float* xr = xall + (pair * STAGES + st) * ROW_ELEMS;

        // --- test indices (warp-uniform) ---
        int person, loc;
        if (is_i64) { person = tests_i32[4 * r]; loc = tests_i32[4 * r + 2]; }
        else        { person = tests_i32[2 * r]; loc = tests_i32[2 * r + 1]; }
        person &= 63;

        // --- person contribution (duplicated per warp): lanes 0..9 own h ---
        // person wire lives at half (person>>5), local row person&31, swizzle key person&7
        const int hh = (lane < 10) ? lane : 0;
        const int pw = person & 7;
        const float* px = &xr[(person >> 5) * 1024 + (person & 31) * 32];
        u64 pcacc = pack2f(cc.b1[hh], 0.f);
        #pragma unroll
        for (int c = 0; c < 8; c++) {
            ulonglong2 pv = *(const ulonglong2*)&px[((c ^ pw) << 2)];   // broadcast
            ffma2(pcacc, pv.x, cc.Wlow[(2 * c) * 10 + hh]);
            ffma2(pcacc, pv.y, cc.Wlow[(2 * c + 1) * 10 + hh]);
        }
        float2 pcp2 = unpack2(pcacc);
        float pcv = pcp2.x + pcp2.y;

        // --- one wire per lane (wire 32q+lane): 10 packed accumulators ---
        u64 acc[10];
        #pragma unroll
        for (int h = 0; h < 10; h++)
            acc[h] = pack2f(__shfl_sync(0xffffffffu, pcv, h), 0.f);

        const float* xw = &xr[q * 1024 + lane * 32];
        #pragma unroll
        for (int c = 0; c < 8; c++) {
            ulonglong2 xa = *(const ulonglong2*)&xw[(c ^ lw) << 2];   // d-pairs 2c,2c+1
            #pragma unroll
            for (int pp = 0; pp < 2; pp++) {
                const u64* wb = &cc.Whigh[(2 * c + pp) * 10];         // uniform LDCU
                u64 xv = pp ? xa.y : xa.x;
                #pragma unroll
                for (int j = 0; j < 10; j++)
                    ffma2(acc[j], xv, wb[j]);
            }
        }

        // --- relu + output layer -> one logit per lane ---
        float lg = b2v;
        #pragma unroll
        for (int h = 0; h < 10; h++) {
            float2 f = unpack2(acc[h]);
            lg += fmaxf(f.x + f.y, 0.f) * cc.W2[h];
        }

        // --- warp-half softmax partials over 32 logits ---
        float mw = lg;
        #pragma unroll
        for (int o = 16; o > 0; o >>= 1)
            mw = fmaxf(mw, __shfl_xor_sync(0xffffffffu, mw, o));
        float sw = __expf(lg - mw);
        #pragma unroll
        for (int o = 16; o > 0; o >>= 1)
            sw += __shfl_xor_sync(0xffffffffu, sw, o);
        float cw = __shfl_sync(0xffffffffu, lg, loc & 31);   // valid if loc half == q

        if (lane == 0) {
            sex[pair][q][0] = mw;
            sex[pair][q][1] = sw;
            sex[pair][q][2] = cw;
        }
        asm volatile("bar.sync %0, 64;" :: "r"(1 + pair) : "memory");   // pair-scoped

        // prefetch row i+2 into the stage just consumed (safe: compute done)
        if (lane == 0 && i + 2 < ITERS && r + 2 < B) {
            mbar_expect_tx(mb_s[st], HALF_BYTES);
            tma_load_half(buf_s[st] + half_off, &tmap,
                          (r + 2) * NUM_WIRES + 32 * q, mb_s[st]);
        }

        if (q == 0 && lane == 0) {
            float m0 = sex[pair][0][0], s0 = sex[pair][0][1], c0 = sex[pair][0][2];
            float m1 = sex[pair][1][0], s1 = sex[pair][1][1], c1 = sex[pair][1][2];
            float m  = fmaxf(m0, m1);
            float s  = s0 * __expf(m0 - m) + s1 * __expf(m1 - m);
            float cand = (loc >> 5) ? c1 : c0;
            out[r] = -(cand - m - __logf(s));
        }
        asm volatile("bar.sync %0, 64;" :: "r"(1 + pair) : "memory");   // sex reuse safe
    }
}

extern "C" void kernel_launch(void* const* d_in, const int* in_sizes, int n_in,
                              void* d_out, int out_size)
{
    const float* outputs = (const float*)d_in[0];
    const int*   tests   = (const int*)d_in[1];
    const float* W1      = (const float*)d_in[2];
    const float* b1      = (const float*)d_in[3];
    const float* W2      = (const float*)d_in[4];
    const float* b2      = (const float*)d_in[5];
    float* out = (float*)d_out;
    int B = out_size;

    // --- weights -> constant memory ---
    prep_kernel<<<1, 192>>>(W1, b1, W2, b2);
    void *src_addr = nullptr, *dst_addr = nullptr;
    cudaGetSymbolAddress(&src_addr, g_pack);
    cudaGetSymbolAddress(&dst_addr, cc);
    cudaMemcpyAsync(dst_addr, src_addr, sizeof(CPack), cudaMemcpyDeviceToDevice, 0);

    // --- build TMA descriptor (driver entry point; no -lcuda needed) ---
    typedef CUresult (*EncodeFn)(CUtensorMap*, CUtensorMapDataType, cuuint32_t, void*,
                                 const cuuint64_t*, const cuuint64_t*, const cuuint32_t*,
                                 const cuuint32_t*, CUtensorMapInterleave, CUtensorMapSwizzle,
                                 CUtensorMapL2promotion, CUtensorMapFloatOOBfill);
    void* fn = nullptr;
    cudaDriverEntryPointQueryResult qres;
    cudaGetDriverEntryPoint("cuTensorMapEncodeTiled", &fn, cudaEnableDefault, &qres);

    CUtensorMap tmap;
    cuuint64_t dims[2]    = {128, (cuuint64_t)B * NUM_WIRES};  // [row bytes, total wires]
    cuuint64_t strides[1] = {128};
    cuuint32_t box[2]     = {128, 32};                         // half row = 4 KB
    cuuint32_t estr[2]    = {1, 1};
    ((EncodeFn)fn)(&tmap, CU_TENSOR_MAP_DATA_TYPE_UINT8, 2, (void*)outputs,
                   dims, strides, box, estr,
                   CU_TENSOR_MAP_INTERLEAVE_NONE, CU_TENSOR_MAP_SWIZZLE_128B,
                   CU_TENSOR_MAP_L2_PROMOTION_L2_128B, CU_TENSOR_MAP_FLOAT_OOB_FILL_NONE);

    // --- launch: dynamic smem ring (4 pairs x 2 stages x 8 KB) + align slack ---
    const int dyn = PAIRS * STAGES * ROW_BYTES + 1024;
    cudaFuncSetAttribute(trainer_kernel, cudaFuncAttributeMaxDynamicSharedMemorySize, dyn);
    int blocks = (B + RPB - 1) / RPB;
    trainer_kernel<<<blocks, NTHREADS, dyn>>>(tmap, tests, out, B);
}